// round 7
// baseline (speedup 1.0000x reference)
#include <cuda_runtime.h>
#include <utility>

using ull = unsigned long long;

namespace tp {

constexpr int LMAX = 4;
constexpr int NM   = 25;    // (L+1)^2
constexpr int NB   = 128;
constexpr int NC   = 128;
constexpr int NCU  = NC / 2;     // 64 f32x2 (ull) elements per (b, m) row
constexpr int MAXNNZ = 8192;

constexpr int iabs(int v) { return v < 0 ? -v : v; }

struct Pat {
  int nnz;
  short seg[MAXNNZ];
  short m1[MAXNNZ];
  short m2[MAXNNZ];
};

// Replicates reference _build_cg_pattern() INCLUDING the sort:
// iteration order (l_out,m_out)->(l1,m1)->(l2,m2) is lexicographic in
// (seg, M1, M2) because seg = l(l+1)+m is monotone in (l, m).
constexpr Pat build_pat() {
  Pat p{};
  int n = 0;
  for (int lo = 0; lo <= LMAX; ++lo)
    for (int mo = -lo; mo <= lo; ++mo)
      for (int l1 = 0; l1 <= LMAX; ++l1)
        for (int u1 = -l1; u1 <= l1; ++u1)
          for (int l2 = 0; l2 <= LMAX; ++l2) {
            if (l2 < iabs(lo - l1) || l2 > lo + l1) continue;
            for (int u2 = -l2; u2 <= l2; ++u2) {
              if (iabs(u1 + u2) == iabs(mo) || iabs(u1 - u2) == iabs(mo)) {
                p.seg[n] = (short)(lo * (lo + 1) + mo);
                p.m1 [n] = (short)(l1 * (l1 + 1) + u1);
                p.m2 [n] = (short)(l2 * (l2 + 1) + u2);
                ++n;
              }
            }
          }
  p.nnz = n;
  return p;
}

constexpr Pat PAT = build_pat();
constexpr int NNZ = PAT.nnz;
static_assert(NNZ > 0 && NNZ < MAXNNZ, "nnz bounds");

constexpr int NG    = 8;   // segment groups (now: one group per CTA)
constexpr int CHUNK = 8;   // cg values prefetched per FMA-chunk

// Flattened pair-major execution plan. FMAs of one (m1,m2) pair are
// consecutive; the first carries the product computation. Same evaluation
// order as R4/R6 (counting-sort pair order) -> bitwise-identical accumulation.
struct Plan {
  int e[NG + 1];
  int mlo[NG], mhi[NG];
  unsigned u1[NG], u2[NG];       // usage bitmasks over m1 / m2
  int fb[NG + 1];                // flat fma ranges per group
  short fseg[MAXNNZ];            // output segment (absolute)
  short fm1[MAXNNZ], fm2[MAXNNZ];
  short ffirst[MAXNNZ];          // 1 = first fma of its pair (compute product)
  short fcgi[MAXNNZ];            // smem cg index (original entry index)
};

// O(nnz) counting sort over pair-id = m1*25+m2 per group.
constexpr Plan build_plan() {
  Plan s{};
  int segstart[NM + 1] = {};
  {
    int pos = 0;
    for (int m = 0; m <= NM; ++m) {
      while (pos < NNZ && PAT.seg[pos] < m) ++pos;
      segstart[m] = pos;
    }
  }
  s.e[0] = 0; s.e[NG] = NNZ;
  for (int g = 1; g < NG; ++g) {
    int target = (NNZ * g) / NG;
    int best = 0, bd = 1 << 30;
    for (int m = 0; m <= NM; ++m) {
      int d = segstart[m] - target; if (d < 0) d = -d;
      if (d < bd) { bd = d; best = segstart[m]; }
    }
    s.e[g] = best;
  }
  int nf = 0;
  for (int g = 0; g < NG; ++g) {
    const int e0 = s.e[g], e1 = s.e[g + 1];
    s.mlo[g] = (e0 < NNZ) ? (int)PAT.seg[e0] : NM;
    s.mhi[g] = (e1 < NNZ) ? (int)PAT.seg[e1] : NM;
    s.fb[g] = nf;
    unsigned u1 = 0, u2 = 0;
    int cnt[NM * NM] = {};
    for (int j = e0; j < e1; ++j) {
      u1 |= 1u << PAT.m1[j];
      u2 |= 1u << PAT.m2[j];
      cnt[PAT.m1[j] * NM + PAT.m2[j]]++;
    }
    int off[NM * NM] = {};
    int base[NM * NM] = {};
    for (int pid = 0; pid < NM * NM; ++pid) {
      if (cnt[pid]) { off[pid] = nf; base[pid] = nf; nf += cnt[pid]; }
    }
    for (int j = e0; j < e1; ++j) {
      int pid = PAT.m1[j] * NM + PAT.m2[j];
      int pos = off[pid]++;
      s.fseg[pos]  = PAT.seg[j];
      s.fm1[pos]   = PAT.m1[j];
      s.fm2[pos]   = PAT.m2[j];
      s.fcgi[pos]  = (short)j;
      s.ffirst[pos] = (short)(pos == base[pid]);
    }
    s.u1[g] = u1; s.u2[g] = u2;
  }
  s.fb[NG] = nf;
  return s;
}

constexpr Plan PLAN = build_plan();

// ---- packed f32x2 math (sm_103a; ptxas never emits these from C++) ----
__device__ __forceinline__ ull mul2(ull a, ull b) {
  ull r;
  asm("mul.rn.f32x2 %0, %1, %2;" : "=l"(r) : "l"(a), "l"(b));
  return r;
}
__device__ __forceinline__ void fma2(ull& d, ull a, ull b) {
  asm("fma.rn.f32x2 %0, %1, %2, %3;" : "=l"(d) : "l"(a), "l"(b), "l"(d));
}

// All PLAN reads below appear ONLY in template-argument position.

template<int OFF>
__device__ __forceinline__ ull ldcg(const ull* __restrict__ scg) {
  return scg[OFF];                         // LDS.64 [scg + literal]
}

template<int FIRST, int A, int B2, int SEGR>
__device__ __forceinline__ void step(ull* __restrict__ acc,
                                     const ull* __restrict__ x1r,
                                     const ull* __restrict__ x2r,
                                     ull& p, ull cgv) {
  if constexpr (FIRST) p = mul2(x1r[A], x2r[B2]);
  fma2(acc[SEGR], cgv, p);
}

template<int MLO, int J0, int... K>
__device__ __forceinline__ void run_chunk(ull* __restrict__ acc,
                                          const ull* __restrict__ x1r,
                                          const ull* __restrict__ x2r,
                                          const ull* __restrict__ scg,
                                          ull& p,
                                          std::integer_sequence<int, K...>) {
  ull cgv[sizeof...(K)];
  ( (cgv[K] = ldcg<PLAN.fcgi[J0 + K]>(scg)), ... );   // independent LDS batch
  ( step<PLAN.ffirst[J0 + K], PLAN.fm1[J0 + K], PLAN.fm2[J0 + K],
         PLAN.fseg[J0 + K] - MLO>(acc, x1r, x2r, p, cgv[K]), ... );
}

template<int MLO, int FB, int FE, int... C>
__device__ __forceinline__ void run_chunks(ull* __restrict__ acc,
                                           const ull* __restrict__ x1r,
                                           const ull* __restrict__ x2r,
                                           const ull* __restrict__ scg,
                                           std::integer_sequence<int, C...>) {
  ull p = 0;
  ( run_chunk<MLO, FB + C * CHUNK>(
        acc, x1r, x2r, scg, p,
        std::make_integer_sequence<int,
            ((FE - (FB + C * CHUNK)) < CHUNK ? (FE - (FB + C * CHUNK)) : CHUNK)>{}),
    ... );
}

template<unsigned MASK, int M>
__device__ __forceinline__ void load1(ull* __restrict__ r,
                                      const ull* __restrict__ src, int c) {
  if constexpr ((MASK >> M) & 1u) r[M] = src[M * NCU + c];
}
template<unsigned MASK, int... M>
__device__ __forceinline__ void loadm(ull* __restrict__ r,
                                      const ull* __restrict__ src, int c,
                                      std::integer_sequence<int, M...>) {
  ( load1<MASK, M>(r, src, c), ... );
}

template<int MLO, int... S>
__device__ __forceinline__ void storem(ull* __restrict__ outu,
                                       const ull* __restrict__ acc, int c,
                                       std::integer_sequence<int, S...>) {
  ( (outu[(MLO + S) * NCU + c] = acc[S]), ... );
}

template<int MLO, int MHI, int FB, int FE, unsigned U1, unsigned U2>
__device__ __forceinline__ void rg(const ull* __restrict__ x1u,
                                   const ull* __restrict__ x2u,
                                   ull* __restrict__ outu,
                                   const ull* __restrict__ scg, int c) {
  ull x1r[NM], x2r[NM];
  loadm<U1>(x1r, x1u, c, std::make_integer_sequence<int, NM>{});
  loadm<U2>(x2r, x2u, c, std::make_integer_sequence<int, NM>{});
  ull acc[MHI - MLO] = {};
  run_chunks<MLO, FB, FE>(
      acc, x1r, x2r, scg,
      std::make_integer_sequence<int, (FE - FB + CHUNK - 1) / CHUNK>{});
  storem<MLO>(outu, acc, c, std::make_integer_sequence<int, MHI - MLO>{});
}

template<int G>
__device__ __forceinline__ void rung(const ull* __restrict__ x1u,
                                     const ull* __restrict__ x2u,
                                     ull* __restrict__ outu,
                                     const ull* __restrict__ scg, int c) {
  rg<PLAN.mlo[G], PLAN.mhi[G], PLAN.fb[G], PLAN.fb[G + 1],
     PLAN.u1[G], PLAN.u2[G]>(x1u, x2u, outu, scg, c);
}

// One GROUP per CTA (uniform across its 8 warps) so each CTA touches only its
// own ~24KB code region -> per-SM I$ working set drops ~4x vs all-groups-in-
// one-CTA. blockIdx.x = g * 32 + quad; warp w handles b = quad*4 + (w>>1),
// channel half = w&1. 256 CTAs, 2 resident per SM (124 regs*512 thr fits 64K).
__global__ void __launch_bounds__(256, 2)
tp_kernel(const float* __restrict__ x1, const float* __restrict__ x2,
          const float* __restrict__ cg, float* __restrict__ out) {
  __shared__ __align__(16) ull scg[NNZ];   // cg duplicated into both f32x2 lanes
  const int tid = threadIdx.x;
  for (int i = tid; i < NNZ; i += 256) {
    ull u = (ull)__float_as_uint(__ldg(cg + i));
    scg[i] = u | (u << 32);
  }
  __syncthreads();

  const int g    = blockIdx.x >> 5;        // group: uniform per CTA
  const int quad = blockIdx.x & 31;        // 4 consecutive b per CTA
  const int wid  = tid >> 5;
  const int b    = quad * 4 + (wid >> 1);
  const int h    = wid & 1;                // channel half
  const int c    = h * 32 + (tid & 31);    // f32x2 lane index within row

  const ull* x1u = reinterpret_cast<const ull*>(x1) + b * (NM * NCU);
  const ull* x2u = reinterpret_cast<const ull*>(x2) + b * (NM * NCU);
  ull*       ou  = reinterpret_cast<ull*>(out)      + b * (NM * NCU);

  switch (g) {
    case 0: rung<0>(x1u, x2u, ou, scg, c); break;
    case 1: rung<1>(x1u, x2u, ou, scg, c); break;
    case 2: rung<2>(x1u, x2u, ou, scg, c); break;
    case 3: rung<3>(x1u, x2u, ou, scg, c); break;
    case 4: rung<4>(x1u, x2u, ou, scg, c); break;
    case 5: rung<5>(x1u, x2u, ou, scg, c); break;
    case 6: rung<6>(x1u, x2u, ou, scg, c); break;
    case 7: rung<7>(x1u, x2u, ou, scg, c); break;
  }
}

// ---- generic fallback (only if runtime nnz != compile-time NNZ) ----
__global__ void tp_generic(const float* __restrict__ x1, const float* __restrict__ x2,
                           const float* __restrict__ cg,
                           const int* __restrict__ M1, const int* __restrict__ M2,
                           const int* __restrict__ seg, int nnz,
                           float* __restrict__ out) {
  const int b = blockIdx.x;
  const int c = threadIdx.x;
  const float* x1b = x1 + b * NM * NC;
  const float* x2b = x2 + b * NM * NC;
  float acc = 0.f;
  int cur = seg[0];
  for (int i = 0; i < nnz; ++i) {
    int s = seg[i];
    if (s != cur) { out[(b * NM + cur) * NC + c] = acc; acc = 0.f; cur = s; }
    acc += cg[i] * x1b[M1[i] * NC + c] * x2b[M2[i] * NC + c];
  }
  out[(b * NM + cur) * NC + c] = acc;
}

}  // namespace tp

extern "C" void kernel_launch(void* const* d_in, const int* in_sizes, int n_in,
                              void* d_out, int out_size) {
  const float* x1 = (const float*)d_in[0];
  const float* x2 = (const float*)d_in[1];
  const float* cg = (const float*)d_in[2];
  const int*   M1 = (const int*)  d_in[3];
  const int*   M2 = (const int*)  d_in[4];
  const int*   sg = (const int*)  d_in[5];
  float* out = (float*)d_out;

  if (in_sizes[2] == tp::NNZ) {
    tp::tp_kernel<<<tp::NG * 32, 256>>>(x1, x2, cg, out);
  } else {
    // pattern mismatch safety net: zero then generic runtime-indexed kernel
    cudaMemsetAsync(d_out, 0, (size_t)out_size * sizeof(float));
    tp::tp_generic<<<tp::NB, tp::NC>>>(x1, x2, cg, M1, M2, sg, in_sizes[2], out);
  }
}

// round 8
// speedup vs baseline: 1.0901x; 1.0901x over previous
#include <cuda_runtime.h>
#include <utility>

using ull = unsigned long long;

namespace tp {

constexpr int LMAX = 4;
constexpr int NM   = 25;    // (L+1)^2
constexpr int NB   = 128;
constexpr int NC   = 128;
constexpr int NCU  = NC / 2;     // 64 f32x2 (ull) elements per (b, m) row
constexpr int MAXNNZ = 8192;

constexpr int iabs(int v) { return v < 0 ? -v : v; }

struct Pat {
  int nnz;
  short seg[MAXNNZ];
  short m1[MAXNNZ];
  short m2[MAXNNZ];
};

// Replicates reference _build_cg_pattern() INCLUDING the sort:
// iteration order (l_out,m_out)->(l1,m1)->(l2,m2) is lexicographic in
// (seg, M1, M2) because seg = l(l+1)+m is monotone in (l, m).
constexpr Pat build_pat() {
  Pat p{};
  int n = 0;
  for (int lo = 0; lo <= LMAX; ++lo)
    for (int mo = -lo; mo <= lo; ++mo)
      for (int l1 = 0; l1 <= LMAX; ++l1)
        for (int u1 = -l1; u1 <= l1; ++u1)
          for (int l2 = 0; l2 <= LMAX; ++l2) {
            if (l2 < iabs(lo - l1) || l2 > lo + l1) continue;
            for (int u2 = -l2; u2 <= l2; ++u2) {
              if (iabs(u1 + u2) == iabs(mo) || iabs(u1 - u2) == iabs(mo)) {
                p.seg[n] = (short)(lo * (lo + 1) + mo);
                p.m1 [n] = (short)(l1 * (l1 + 1) + u1);
                p.m2 [n] = (short)(l2 * (l2 + 1) + u2);
                ++n;
              }
            }
          }
  p.nnz = n;
  return p;
}

constexpr Pat PAT = build_pat();
constexpr int NNZ = PAT.nnz;
static_assert(NNZ > 0 && NNZ < MAXNNZ, "nnz bounds");

constexpr int NG    = 8;   // segment groups (one warp per group per channel-half)
constexpr int CHUNK = 4;   // FMAs per software-pipeline stage (1x LDS.128 pair)

// Flattened pair-major execution plan. FMAs of one (m1,m2) pair are
// consecutive; the first carries the product computation. Same evaluation
// order as R4/R6 (counting-sort pair order) -> bitwise-identical accumulation.
struct Plan {
  int e[NG + 1];
  int mlo[NG], mhi[NG];
  unsigned u1[NG], u2[NG];       // usage bitmasks over m1 / m2
  int fb[NG + 1];                // flat fma ranges per group
  short fseg[MAXNNZ];            // output segment (absolute)
  short fm1[MAXNNZ], fm2[MAXNNZ];
  short ffirst[MAXNNZ];          // 1 = first fma of its pair (compute product)
  short fcgi[MAXNNZ];            // original cg index of each fma
};

// O(nnz) counting sort over pair-id = m1*25+m2 per group.
constexpr Plan build_plan() {
  Plan s{};
  int segstart[NM + 1] = {};
  {
    int pos = 0;
    for (int m = 0; m <= NM; ++m) {
      while (pos < NNZ && PAT.seg[pos] < m) ++pos;
      segstart[m] = pos;
    }
  }
  s.e[0] = 0; s.e[NG] = NNZ;
  for (int g = 1; g < NG; ++g) {
    int target = (NNZ * g) / NG;
    int best = 0, bd = 1 << 30;
    for (int m = 0; m <= NM; ++m) {
      int d = segstart[m] - target; if (d < 0) d = -d;
      if (d < bd) { bd = d; best = segstart[m]; }
    }
    s.e[g] = best;
  }
  int nf = 0;
  for (int g = 0; g < NG; ++g) {
    const int e0 = s.e[g], e1 = s.e[g + 1];
    s.mlo[g] = (e0 < NNZ) ? (int)PAT.seg[e0] : NM;
    s.mhi[g] = (e1 < NNZ) ? (int)PAT.seg[e1] : NM;
    s.fb[g] = nf;
    unsigned u1 = 0, u2 = 0;
    int cnt[NM * NM] = {};
    for (int j = e0; j < e1; ++j) {
      u1 |= 1u << PAT.m1[j];
      u2 |= 1u << PAT.m2[j];
      cnt[PAT.m1[j] * NM + PAT.m2[j]]++;
    }
    int off[NM * NM] = {};
    int base[NM * NM] = {};
    for (int pid = 0; pid < NM * NM; ++pid) {
      if (cnt[pid]) { off[pid] = nf; base[pid] = nf; nf += cnt[pid]; }
    }
    for (int j = e0; j < e1; ++j) {
      int pid = PAT.m1[j] * NM + PAT.m2[j];
      int pos = off[pid]++;
      s.fseg[pos]  = PAT.seg[j];
      s.fm1[pos]   = PAT.m1[j];
      s.fm2[pos]   = PAT.m2[j];
      s.fcgi[pos]  = (short)j;
      s.ffirst[pos] = (short)(pos == base[pid]);
    }
    s.u1[g] = u1; s.u2[g] = u2;
  }
  s.fb[NG] = nf;
  return s;
}

constexpr Plan PLAN = build_plan();

// Packed cg layout: plan order, each group padded to a CHUNK multiple so every
// chunk is a 16B-aligned pair of LDS.128-able ulonglong2 slots.
struct Pack {
  int pfb[NG + 1];
  int delta[NG];                    // packed_pos - plan_pos per group
  short idx[MAXNNZ + CHUNK * NG];   // packed position -> original cg index
  int total;
};

constexpr Pack build_pack() {
  Pack k{};
  int p = 0;
  for (int g = 0; g < NG; ++g) {
    k.pfb[g] = p;
    k.delta[g] = p - PLAN.fb[g];
    const int len = PLAN.fb[g + 1] - PLAN.fb[g];
    for (int i = 0; i < len; ++i) k.idx[p + i] = PLAN.fcgi[PLAN.fb[g] + i];
    p += (len + CHUNK - 1) / CHUNK * CHUNK;
  }
  k.pfb[NG] = p;
  k.total = p;
  return k;
}

constexpr Pack PK = build_pack();
constexpr int NF2 = PK.total;

// Runtime copy of the packed index map (constexpr-initialized __device__
// global: static data, no allocation).
struct IdxArr { short v[MAXNNZ + CHUNK * NG]; };
constexpr IdxArr make_idx() {
  IdxArr a{};
  for (int i = 0; i < MAXNNZ + CHUNK * NG; ++i) a.v[i] = PK.idx[i];
  return a;
}
__device__ const IdxArr d_pidx = make_idx();

// ---- packed f32x2 math (sm_103a; ptxas never emits these from C++) ----
__device__ __forceinline__ ull mul2(ull a, ull b) {
  ull r;
  asm("mul.rn.f32x2 %0, %1, %2;" : "=l"(r) : "l"(a), "l"(b));
  return r;
}
__device__ __forceinline__ void fma2(ull& d, ull a, ull b) {
  asm("fma.rn.f32x2 %0, %1, %2, %3;" : "=l"(d) : "l"(a), "l"(b), "l"(d));
}

// All PLAN/PK reads below appear ONLY in template-argument position.

template<int FIRST, int A, int B2, int SEGR>
__device__ __forceinline__ void step(ull* __restrict__ acc,
                                     const ull* __restrict__ x1r,
                                     const ull* __restrict__ x2r,
                                     ull& p, ull cgv) {
  if constexpr (FIRST) p = mul2(x1r[A], x2r[B2]);
  fma2(acc[SEGR], cgv, p);
}

// Load one full chunk (4 packed cg) with two LDS.128. PPOS is a multiple of 4
// (group bases padded), and padding slots are initialized, so over-read of the
// tail is always safe.
template<int PPOS>
__device__ __forceinline__ void load_chunk(ull* __restrict__ buf,
                                           const ull* __restrict__ scg) {
  const ulonglong2* v = reinterpret_cast<const ulonglong2*>(scg);
  ulonglong2 a = v[PPOS / 2];
  ulonglong2 b = v[PPOS / 2 + 1];
  buf[0] = a.x; buf[1] = a.y; buf[2] = b.x; buf[3] = b.y;
}

template<int MLO, int POS, int... K>
__device__ __forceinline__ void compute_chunk(ull* __restrict__ acc,
                                              const ull* __restrict__ x1r,
                                              const ull* __restrict__ x2r,
                                              ull& p, const ull* __restrict__ buf,
                                              std::integer_sequence<int, K...>) {
  ( step<PLAN.ffirst[POS + K], PLAN.fm1[POS + K], PLAN.fm2[POS + K],
         PLAN.fseg[POS + K] - MLO>(acc, x1r, x2r, p, buf[K]), ... );
}

// Double-buffered software pipeline: while computing chunk at POS (in bufA),
// chunk POS+CHUNK is being loaded (into bufB). Load is data-independent of
// current compute, so LDS latency overlaps the math.
template<int MLO, int FE, int DELTA, int POS, int BUF>
__device__ __forceinline__ void pipe(ull* __restrict__ acc,
                                     const ull* __restrict__ x1r,
                                     const ull* __restrict__ x2r,
                                     const ull* __restrict__ scg, ull& p,
                                     ull (&b0)[CHUNK], ull (&b1)[CHUNK]) {
  constexpr int N = (FE - POS < CHUNK) ? (FE - POS) : CHUNK;
  if constexpr (POS + N < FE)
    load_chunk<POS + N + DELTA>(BUF ? b0 : b1, scg);
  compute_chunk<MLO, POS>(acc, x1r, x2r, p, BUF ? b1 : b0,
                          std::make_integer_sequence<int, N>{});
  if constexpr (POS + N < FE)
    pipe<MLO, FE, DELTA, POS + N, BUF ^ 1>(acc, x1r, x2r, scg, p, b0, b1);
}

template<unsigned MASK, int M>
__device__ __forceinline__ void load1(ull* __restrict__ r,
                                      const ull* __restrict__ src, int c) {
  if constexpr ((MASK >> M) & 1u) r[M] = src[M * NCU + c];
}
template<unsigned MASK, int... M>
__device__ __forceinline__ void loadm(ull* __restrict__ r,
                                      const ull* __restrict__ src, int c,
                                      std::integer_sequence<int, M...>) {
  ( load1<MASK, M>(r, src, c), ... );
}

template<int MLO, int... S>
__device__ __forceinline__ void storem(ull* __restrict__ outu,
                                       const ull* __restrict__ acc, int c,
                                       std::integer_sequence<int, S...>) {
  ( (outu[(MLO + S) * NCU + c] = acc[S]), ... );
}

template<int MLO, int MHI, int FB, int FE, int DELTA, unsigned U1, unsigned U2>
__device__ __forceinline__ void rg(const ull* __restrict__ x1u,
                                   const ull* __restrict__ x2u,
                                   ull* __restrict__ outu,
                                   const ull* __restrict__ scg, int c) {
  ull x1r[NM], x2r[NM];
  loadm<U1>(x1r, x1u, c, std::make_integer_sequence<int, NM>{});
  loadm<U2>(x2r, x2u, c, std::make_integer_sequence<int, NM>{});
  ull acc[MHI - MLO] = {};
  ull b0[CHUNK], b1[CHUNK];
  load_chunk<FB + DELTA>(b0, scg);
  ull p = 0;
  pipe<MLO, FE, DELTA, FB, 0>(acc, x1r, x2r, scg, p, b0, b1);
  storem<MLO>(outu, acc, c, std::make_integer_sequence<int, MHI - MLO>{});
}

template<int G>
__device__ __forceinline__ void rung(const ull* __restrict__ x1u,
                                     const ull* __restrict__ x2u,
                                     ull* __restrict__ outu,
                                     const ull* __restrict__ scg, int c) {
  rg<PLAN.mlo[G], PLAN.mhi[G], PLAN.fb[G], PLAN.fb[G + 1], PK.delta[G],
     PLAN.u1[G], PLAN.u2[G]>(x1u, x2u, outu, scg, c);
}

// 512 threads = 16 warps = 8 groups x 2 channel-halves; grid = 128 -> exactly
// one CTA per SM (single uniform wave).
__global__ void __launch_bounds__(512, 1)
tp_kernel(const float* __restrict__ x1, const float* __restrict__ x2,
          const float* __restrict__ cg, float* __restrict__ out) {
  // cg reordered to packed plan order, duplicated into both f32x2 lanes
  __shared__ __align__(16) ull scg[NF2];
  const int tid = threadIdx.x;
  for (int i = tid; i < NF2; i += 512) {
    ull u = (ull)__float_as_uint(__ldg(cg + d_pidx.v[i]));
    scg[i] = u | (u << 32);
  }
  __syncthreads();

  const int b   = blockIdx.x;
  const int wid = tid >> 5;
  const int g   = wid & 7;                 // segment group
  const int h   = wid >> 3;                // channel half
  const int c   = h * 32 + (tid & 31);     // f32x2 lane index within row

  const ull* x1u = reinterpret_cast<const ull*>(x1) + b * (NM * NCU);
  const ull* x2u = reinterpret_cast<const ull*>(x2) + b * (NM * NCU);
  ull*       ou  = reinterpret_cast<ull*>(out)      + b * (NM * NCU);

  switch (g) {
    case 0: rung<0>(x1u, x2u, ou, scg, c); break;
    case 1: rung<1>(x1u, x2u, ou, scg, c); break;
    case 2: rung<2>(x1u, x2u, ou, scg, c); break;
    case 3: rung<3>(x1u, x2u, ou, scg, c); break;
    case 4: rung<4>(x1u, x2u, ou, scg, c); break;
    case 5: rung<5>(x1u, x2u, ou, scg, c); break;
    case 6: rung<6>(x1u, x2u, ou, scg, c); break;
    case 7: rung<7>(x1u, x2u, ou, scg, c); break;
  }
}

// ---- generic fallback (only if runtime nnz != compile-time NNZ) ----
__global__ void tp_generic(const float* __restrict__ x1, const float* __restrict__ x2,
                           const float* __restrict__ cg,
                           const int* __restrict__ M1, const int* __restrict__ M2,
                           const int* __restrict__ seg, int nnz,
                           float* __restrict__ out) {
  const int b = blockIdx.x;
  const int c = threadIdx.x;
  const float* x1b = x1 + b * NM * NC;
  const float* x2b = x2 + b * NM * NC;
  float acc = 0.f;
  int cur = seg[0];
  for (int i = 0; i < nnz; ++i) {
    int s = seg[i];
    if (s != cur) { out[(b * NM + cur) * NC + c] = acc; acc = 0.f; cur = s; }
    acc += cg[i] * x1b[M1[i] * NC + c] * x2b[M2[i] * NC + c];
  }
  out[(b * NM + cur) * NC + c] = acc;
}

}  // namespace tp

extern "C" void kernel_launch(void* const* d_in, const int* in_sizes, int n_in,
                              void* d_out, int out_size) {
  const float* x1 = (const float*)d_in[0];
  const float* x2 = (const float*)d_in[1];
  const float* cg = (const float*)d_in[2];
  const int*   M1 = (const int*)  d_in[3];
  const int*   M2 = (const int*)  d_in[4];
  const int*   sg = (const int*)  d_in[5];
  float* out = (float*)d_out;

  if (in_sizes[2] == tp::NNZ) {
    tp::tp_kernel<<<tp::NB, 512>>>(x1, x2, cg, out);
  } else {
    // pattern mismatch safety net: zero then generic runtime-indexed kernel
    cudaMemsetAsync(d_out, 0, (size_t)out_size * sizeof(float));
    tp::tp_generic<<<tp::NB, tp::NC>>>(x1, x2, cg, M1, M2, sg, in_sizes[2], out);
  }
}

// round 9
// speedup vs baseline: 1.2081x; 1.1083x over previous
#include <cuda_runtime.h>
#include <utility>

using ull = unsigned long long;

namespace tp {

constexpr int LMAX = 4;
constexpr int NM   = 25;    // (L+1)^2
constexpr int NB   = 128;
constexpr int NC   = 128;
constexpr int NCU  = NC / 2;     // 64 f32x2 (ull) elements per (b, m) row
constexpr int MAXNNZ = 8192;

constexpr int iabs(int v) { return v < 0 ? -v : v; }

struct Pat {
  int nnz;
  short seg[MAXNNZ];
  short m1[MAXNNZ];
  short m2[MAXNNZ];
};

// Replicates reference _build_cg_pattern() INCLUDING the sort.
constexpr Pat build_pat() {
  Pat p{};
  int n = 0;
  for (int lo = 0; lo <= LMAX; ++lo)
    for (int mo = -lo; mo <= lo; ++mo)
      for (int l1 = 0; l1 <= LMAX; ++l1)
        for (int u1 = -l1; u1 <= l1; ++u1)
          for (int l2 = 0; l2 <= LMAX; ++l2) {
            if (l2 < iabs(lo - l1) || l2 > lo + l1) continue;
            for (int u2 = -l2; u2 <= l2; ++u2) {
              if (iabs(u1 + u2) == iabs(mo) || iabs(u1 - u2) == iabs(mo)) {
                p.seg[n] = (short)(lo * (lo + 1) + mo);
                p.m1 [n] = (short)(l1 * (l1 + 1) + u1);
                p.m2 [n] = (short)(l2 * (l2 + 1) + u2);
                ++n;
              }
            }
          }
  p.nnz = n;
  return p;
}

constexpr Pat PAT = build_pat();
constexpr int NNZ = PAT.nnz;
static_assert(NNZ > 0 && NNZ < MAXNNZ, "nnz bounds");

constexpr int NG    = 8;   // segment groups (one warp per group per channel-half)
constexpr int CHUNK = 8;   // cg values per batch (4x LDS.128)

// Flattened pair-major execution plan (same evaluation order as R4/R6 ->
// bitwise-identical accumulation; rel_err is the canary).
struct Plan {
  int e[NG + 1];
  int mlo[NG], mhi[NG];
  unsigned u1[NG], u2[NG];
  int fb[NG + 1];
  short fseg[MAXNNZ];
  short fm1[MAXNNZ], fm2[MAXNNZ];
  short ffirst[MAXNNZ];
  short fcgi[MAXNNZ];
};

constexpr Plan build_plan() {
  Plan s{};
  int segstart[NM + 1] = {};
  {
    int pos = 0;
    for (int m = 0; m <= NM; ++m) {
      while (pos < NNZ && PAT.seg[pos] < m) ++pos;
      segstart[m] = pos;
    }
  }
  s.e[0] = 0; s.e[NG] = NNZ;
  for (int g = 1; g < NG; ++g) {
    int target = (NNZ * g) / NG;
    int best = 0, bd = 1 << 30;
    for (int m = 0; m <= NM; ++m) {
      int d = segstart[m] - target; if (d < 0) d = -d;
      if (d < bd) { bd = d; best = segstart[m]; }
    }
    s.e[g] = best;
  }
  int nf = 0;
  for (int g = 0; g < NG; ++g) {
    const int e0 = s.e[g], e1 = s.e[g + 1];
    s.mlo[g] = (e0 < NNZ) ? (int)PAT.seg[e0] : NM;
    s.mhi[g] = (e1 < NNZ) ? (int)PAT.seg[e1] : NM;
    s.fb[g] = nf;
    unsigned u1 = 0, u2 = 0;
    int cnt[NM * NM] = {};
    for (int j = e0; j < e1; ++j) {
      u1 |= 1u << PAT.m1[j];
      u2 |= 1u << PAT.m2[j];
      cnt[PAT.m1[j] * NM + PAT.m2[j]]++;
    }
    int off[NM * NM] = {};
    int base[NM * NM] = {};
    for (int pid = 0; pid < NM * NM; ++pid) {
      if (cnt[pid]) { off[pid] = nf; base[pid] = nf; nf += cnt[pid]; }
    }
    for (int j = e0; j < e1; ++j) {
      int pid = PAT.m1[j] * NM + PAT.m2[j];
      int pos = off[pid]++;
      s.fseg[pos]  = PAT.seg[j];
      s.fm1[pos]   = PAT.m1[j];
      s.fm2[pos]   = PAT.m2[j];
      s.fcgi[pos]  = (short)j;
      s.ffirst[pos] = (short)(pos == base[pid]);
    }
    s.u1[g] = u1; s.u2[g] = u2;
  }
  s.fb[NG] = nf;
  return s;
}

constexpr Plan PLAN = build_plan();

// Packed cg layout: plan order, group bases padded to CHUNK so every batch is
// 16B-aligned LDS.128-able, tail over-read safe.
struct Pack {
  int delta[NG];                    // packed_pos - plan_pos per group
  short idx[MAXNNZ + CHUNK * NG];   // packed position -> original cg index
  int total;
};

constexpr Pack build_pack() {
  Pack k{};
  int p = 0;
  for (int g = 0; g < NG; ++g) {
    k.delta[g] = p - PLAN.fb[g];
    const int len = PLAN.fb[g + 1] - PLAN.fb[g];
    for (int i = 0; i < len; ++i) k.idx[p + i] = PLAN.fcgi[PLAN.fb[g] + i];
    p += (len + CHUNK - 1) / CHUNK * CHUNK;
  }
  k.total = p;
  return k;
}

constexpr Pack PK = build_pack();
constexpr int NF2 = PK.total;

// Runtime copy of the packed index map (constexpr-initialized static data).
struct IdxArr { short v[MAXNNZ + CHUNK * NG]; };
constexpr IdxArr make_idx() {
  IdxArr a{};
  for (int i = 0; i < MAXNNZ + CHUNK * NG; ++i) a.v[i] = PK.idx[i];
  return a;
}
__device__ const IdxArr d_pidx = make_idx();

// ---- packed f32x2 math (sm_103a) ----
__device__ __forceinline__ ull mul2(ull a, ull b) {
  ull r;
  asm("mul.rn.f32x2 %0, %1, %2;" : "=l"(r) : "l"(a), "l"(b));
  return r;
}
__device__ __forceinline__ void fma2(ull& d, ull a, ull b) {
  asm("fma.rn.f32x2 %0, %1, %2, %3;" : "=l"(d) : "l"(a), "l"(b), "l"(d));
}

// All PLAN/PK reads appear ONLY in template-argument position.

// x1 stays in registers; x2 comes from the CTA's smem tile at point of use
// (identical value -> bitwise-identical product; frees ~50 registers).
template<int FIRST, int A, int B2, int SEGR>
__device__ __forceinline__ void step(ull* __restrict__ acc,
                                     const ull* __restrict__ x1r,
                                     const ull* __restrict__ scx2, int c,
                                     ull& p, ull cgv) {
  if constexpr (FIRST) p = mul2(x1r[A], scx2[B2 * NCU + c]);
  fma2(acc[SEGR], cgv, p);
}

// Batch-load N (<=CHUNK) packed cg values; PPOS is CHUNK-aligned, padding makes
// over-read of the tail safe.
template<int PPOS, int N>
__device__ __forceinline__ void load_cg(ull* __restrict__ buf,
                                        const ull* __restrict__ scg) {
  const ulonglong2* v = reinterpret_cast<const ulonglong2*>(scg + PPOS);
#pragma unroll
  for (int i = 0; i < (N + 1) / 2; ++i) {
    ulonglong2 t = v[i];
    buf[2 * i] = t.x; buf[2 * i + 1] = t.y;
  }
}

template<int MLO, int POS, int DELTA, int... K>
__device__ __forceinline__ void run_chunk(ull* __restrict__ acc,
                                          const ull* __restrict__ x1r,
                                          const ull* __restrict__ scx2, int c,
                                          const ull* __restrict__ scg, ull& p,
                                          std::integer_sequence<int, K...>) {
  ull cgv[CHUNK];
  load_cg<POS + DELTA, sizeof...(K)>(cgv, scg);
  ( step<PLAN.ffirst[POS + K], PLAN.fm1[POS + K], PLAN.fm2[POS + K],
         PLAN.fseg[POS + K] - MLO>(acc, x1r, scx2, c, p, cgv[K]), ... );
}

template<int MLO, int FB, int FE, int DELTA, int... C>
__device__ __forceinline__ void run_chunks(ull* __restrict__ acc,
                                           const ull* __restrict__ x1r,
                                           const ull* __restrict__ scx2, int c,
                                           const ull* __restrict__ scg,
                                           std::integer_sequence<int, C...>) {
  ull p = 0;
  ( run_chunk<MLO, FB + C * CHUNK, DELTA>(
        acc, x1r, scx2, c, scg, p,
        std::make_integer_sequence<int,
            ((FE - (FB + C * CHUNK)) < CHUNK ? (FE - (FB + C * CHUNK)) : CHUNK)>{}),
    ... );
}

template<unsigned MASK, int M>
__device__ __forceinline__ void load1(ull* __restrict__ r,
                                      const ull* __restrict__ src, int c) {
  if constexpr ((MASK >> M) & 1u) r[M] = src[M * NCU + c];
}
template<unsigned MASK, int... M>
__device__ __forceinline__ void loadm(ull* __restrict__ r,
                                      const ull* __restrict__ src, int c,
                                      std::integer_sequence<int, M...>) {
  ( load1<MASK, M>(r, src, c), ... );
}

template<int MLO, int... S>
__device__ __forceinline__ void storem(ull* __restrict__ outu,
                                       const ull* __restrict__ acc, int c,
                                       std::integer_sequence<int, S...>) {
  ( (outu[(MLO + S) * NCU + c] = acc[S]), ... );
}

template<int MLO, int MHI, int FB, int FE, int DELTA, unsigned U1>
__device__ __forceinline__ void rg(const ull* __restrict__ x1u,
                                   const ull* __restrict__ scx2,
                                   ull* __restrict__ outu,
                                   const ull* __restrict__ scg, int c) {
  ull x1r[NM];
  loadm<U1>(x1r, x1u, c, std::make_integer_sequence<int, NM>{});
  ull acc[MHI - MLO] = {};
  run_chunks<MLO, FB, FE, DELTA>(
      acc, x1r, scx2, c, scg,
      std::make_integer_sequence<int, (FE - FB + CHUNK - 1) / CHUNK>{});
  storem<MLO>(outu, acc, c, std::make_integer_sequence<int, MHI - MLO>{});
}

template<int G>
__device__ __forceinline__ void rung(const ull* __restrict__ x1u,
                                     const ull* __restrict__ scx2,
                                     ull* __restrict__ outu,
                                     const ull* __restrict__ scg, int c) {
  rg<PLAN.mlo[G], PLAN.mhi[G], PLAN.fb[G], PLAN.fb[G + 1], PK.delta[G],
     PLAN.u1[G]>(x1u, scx2, outu, scg, c);
}

// 512 threads = 16 warps = 8 groups x 2 channel-halves; grid = 128 -> exactly
// one CTA per SM. x2 tile staged in smem; x1 in registers.
__global__ void __launch_bounds__(512, 1)
tp_kernel(const float* __restrict__ x1, const float* __restrict__ x2,
          const float* __restrict__ cg, float* __restrict__ out) {
  __shared__ __align__(16) ull scg[NF2];          // packed cg, f32x2-duplicated
  __shared__ __align__(16) ull scx2[NM * NCU];    // x2 tile for this b
  const int tid = threadIdx.x;
  const int b   = blockIdx.x;

  const ull* x1u = reinterpret_cast<const ull*>(x1) + b * (NM * NCU);
  const ull* x2u = reinterpret_cast<const ull*>(x2) + b * (NM * NCU);
  ull*       ou  = reinterpret_cast<ull*>(out)      + b * (NM * NCU);

  for (int i = tid; i < NF2; i += 512) {
    ull u = (ull)__float_as_uint(__ldg(cg + d_pidx.v[i]));
    scg[i] = u | (u << 32);
  }
  for (int i = tid; i < NM * NCU; i += 512) scx2[i] = x2u[i];
  __syncthreads();

  const int wid = tid >> 5;
  const int g   = wid & 7;                 // segment group
  const int h   = wid >> 3;                // channel half
  const int c   = h * 32 + (tid & 31);     // f32x2 lane index within row

  switch (g) {
    case 0: rung<0>(x1u, scx2, ou, scg, c); break;
    case 1: rung<1>(x1u, scx2, ou, scg, c); break;
    case 2: rung<2>(x1u, scx2, ou, scg, c); break;
    case 3: rung<3>(x1u, scx2, ou, scg, c); break;
    case 4: rung<4>(x1u, scx2, ou, scg, c); break;
    case 5: rung<5>(x1u, scx2, ou, scg, c); break;
    case 6: rung<6>(x1u, scx2, ou, scg, c); break;
    case 7: rung<7>(x1u, scx2, ou, scg, c); break;
  }
}

// ---- generic fallback (only if runtime nnz != compile-time NNZ) ----
__global__ void tp_generic(const float* __restrict__ x1, const float* __restrict__ x2,
                           const float* __restrict__ cg,
                           const int* __restrict__ M1, const int* __restrict__ M2,
                           const int* __restrict__ seg, int nnz,
                           float* __restrict__ out) {
  const int b = blockIdx.x;
  const int c = threadIdx.x;
  const float* x1b = x1 + b * NM * NC;
  const float* x2b = x2 + b * NM * NC;
  float acc = 0.f;
  int cur = seg[0];
  for (int i = 0; i < nnz; ++i) {
    int s = seg[i];
    if (s != cur) { out[(b * NM + cur) * NC + c] = acc; acc = 0.f; cur = s; }
    acc += cg[i] * x1b[M1[i] * NC + c] * x2b[M2[i] * NC + c];
  }
  out[(b * NM + cur) * NC + c] = acc;
}

}  // namespace tp

extern "C" void kernel_launch(void* const* d_in, const int* in_sizes, int n_in,
                              void* d_out, int out_size) {
  const float* x1 = (const float*)d_in[0];
  const float* x2 = (const float*)d_in[1];
  const float* cg = (const float*)d_in[2];
  const int*   M1 = (const int*)  d_in[3];
  const int*   M2 = (const int*)  d_in[4];
  const int*   sg = (const int*)  d_in[5];
  float* out = (float*)d_out;

  if (in_sizes[2] == tp::NNZ) {
    tp::tp_kernel<<<tp::NB, 512>>>(x1, x2, cg, out);
  } else {
    cudaMemsetAsync(d_out, 0, (size_t)out_size * sizeof(float));
    tp::tp_generic<<<tp::NB, tp::NC>>>(x1, x2, cg, M1, M2, sg, in_sizes[2], out);
  }
}